// round 16
// baseline (speedup 1.0000x reference)
#include <cuda_runtime.h>
#include <cstdint>
#include <math.h>

#define B_  4
#define S_  2048
#define D_  768
#define H_  12
#define E_  64
#define BS_ (B_ * S_)   // 8192

// Scratch (static device globals: allocation-free per harness rules)
__device__ float g_q[(size_t)B_ * H_ * S_ * E_];   // [bh][s][e-interleaved]
__device__ float g_k[(size_t)B_ * H_ * S_ * E_];   // [bh][s][e-interleaved]
__device__ float g_vt[(size_t)B_ * H_ * E_ * S_];  // [bh][e][s-interleaved]
__device__ float g_z[(size_t)BS_ * D_];
__device__ float g_xt [(size_t)BS_ * D_];          // x, tf32-rounded
__device__ float g_wqr[(size_t)H_ * D_ * E_];      // W_Q, tf32-rounded
__device__ float g_wkr[(size_t)H_ * D_ * E_];
__device__ float g_wvr[(size_t)H_ * D_ * E_];
__device__ float g_wor[(size_t)D_ * D_];           // W_O, tf32-rounded

// ---------------------------------------------------------------------------
__device__ __forceinline__ unsigned tf32cvt(float f) {
    unsigned u;
    asm("cvt.rna.tf32.f32 %0, %1;" : "=r"(u) : "f"(f));
    return u;
}

__device__ __forceinline__ void mma8(float c[4],
                                     unsigned a0, unsigned a1, unsigned a2, unsigned a3,
                                     unsigned b0, unsigned b1) {
    asm volatile(
        "mma.sync.aligned.m16n8k8.row.col.f32.tf32.tf32.f32 "
        "{%0,%1,%2,%3}, {%4,%5,%6,%7}, {%8,%9}, {%0,%1,%2,%3};\n"
        : "+f"(c[0]), "+f"(c[1]), "+f"(c[2]), "+f"(c[3])
        : "r"(a0), "r"(a1), "r"(a2), "r"(a3), "r"(b0), "r"(b1));
}

__device__ __forceinline__ uint32_t smem_u32(const void* p) {
    uint32_t a;
    asm("{ .reg .u64 t; cvta.to.shared.u64 t, %1; cvt.u32.u64 %0, t; }" : "=r"(a) : "l"(p));
    return a;
}

__device__ __forceinline__ void cp16(uint32_t dst, const void* src) {
    asm volatile("cp.async.cg.shared.global [%0], [%1], 16;" :: "r"(dst), "l"(src));
}
#define CP_COMMIT() asm volatile("cp.async.commit_group;" ::: "memory")
#define CP_WAIT0()  asm volatile("cp.async.wait_group 0;" ::: "memory")
#define CP_WAIT1()  asm volatile("cp.async.wait_group 1;" ::: "memory")

// pair-interleave within 8-groups: w -> (w<4 ? 2w : 2w-7)
__device__ __forceinline__ int perm8(int w) { return (w < 4) ? 2 * w : 2 * w - 7; }

// ---------------------------------------------------------------------------
__global__ void __launch_bounds__(256) round_tf32(
    const float* __restrict__ s, float* __restrict__ d, int n4)
{
    int i = blockIdx.x * 256 + threadIdx.x;
    if (i < n4) {
        float4 f = reinterpret_cast<const float4*>(s)[i];
        uint4 u = { tf32cvt(f.x), tf32cvt(f.y), tf32cvt(f.z), tf32cvt(f.w) };
        reinterpret_cast<uint4*>(d)[i] = u;
    }
}

// ---------------------------------------------------------------------------
// cp.async double-buffered GEMM core (unchanged from round 15).
// ---------------------------------------------------------------------------
#define A_W(b)   ((b) * 4608)
#define B_W(b)   (9216 + (b) * 2304)
#define G_SMEM_B 55296

__device__ __forceinline__ void g_tile_ca(
    unsigned* sm, int buf, const float* __restrict__ Asrc,
    const float* __restrict__ Bsrc, int bstride, int tid, int k0)
{
    #pragma unroll
    for (int i = 0; i < 4; ++i) {
        int idx = tid + i * 256;
        int r = idx >> 3, c4 = (idx & 7) * 4;
        cp16(smem_u32(&sm[A_W(buf) + r * 36 + c4]),
             Asrc + (size_t)r * D_ + k0 + c4);
    }
    #pragma unroll
    for (int i = 0; i < 2; ++i) {
        int idx = tid + i * 256;
        int r = idx >> 4, c4 = (idx & 15) * 4;
        cp16(smem_u32(&sm[B_W(buf) + r * 72 + c4]),
             Bsrc + (size_t)(k0 + r) * bstride + c4);
    }
}

__device__ __forceinline__ void g_compute(
    const unsigned* sm, int buf, int wm, int wn, int lane, float acc[2][4][4])
{
    const unsigned* As = sm + A_W(buf);
    const unsigned* Bs = sm + B_W(buf);
    #pragma unroll
    for (int kk = 0; kk < 4; ++kk) {
        const int ac = kk * 8 + (lane & 3);
        const int ar = wm * 32 + (lane >> 2);
        unsigned a[2][4];
        #pragma unroll
        for (int mt = 0; mt < 2; ++mt) {
            a[mt][0] = As[(ar + mt * 16    ) * 36 + ac];
            a[mt][1] = As[(ar + mt * 16 + 8) * 36 + ac];
            a[mt][2] = As[(ar + mt * 16    ) * 36 + ac + 4];
            a[mt][3] = As[(ar + mt * 16 + 8) * 36 + ac + 4];
        }
        const int bk = kk * 8 + (lane & 3);
        const int bn = wn * 32 + (lane >> 2);
        unsigned b[4][2];
        #pragma unroll
        for (int nt = 0; nt < 4; ++nt) {
            b[nt][0] = Bs[bk * 72 + bn + nt * 8];
            b[nt][1] = Bs[(bk + 4) * 72 + bn + nt * 8];
        }
        #pragma unroll
        for (int mt = 0; mt < 2; ++mt)
            #pragma unroll
            for (int nt = 0; nt < 4; ++nt)
                mma8(acc[mt][nt], a[mt][0], a[mt][1], a[mt][2], a[mt][3],
                     b[nt][0], b[nt][1]);
    }
}

// QKV projection: grid (64, H, 3). Q/K stored e-interleaved; V transposed,
// s-interleaved. All values tf32-rounded (consumed raw by attn).
__global__ void __launch_bounds__(256, 4) qkv_gemm(
    const float* __restrict__ bQ, const float* __restrict__ bK, const float* __restrict__ bV,
    float* __restrict__ q, float* __restrict__ k, float* __restrict__ vt)
{
    extern __shared__ unsigned sm[];
    const int row0 = blockIdx.x * 128;
    const int h    = blockIdx.y;
    const int m    = blockIdx.z;
    const int tid  = threadIdx.x;
    const int lane = tid & 31;
    const int wid  = tid >> 5;
    const int wm   = wid >> 1, wn = wid & 1;

    const float* Asrc = g_xt + (size_t)row0 * D_;
    const float* W    = (m == 0 ? g_wqr : m == 1 ? g_wkr : g_wvr) + (size_t)h * D_ * E_;
    const float* bias = m == 0 ? bQ : m == 1 ? bK : bV;

    float acc[2][4][4] = {};

    g_tile_ca(sm, 0, Asrc, W, E_, tid, 0);
    CP_COMMIT();
    for (int t = 0; t < 24; ++t) {
        if (t + 1 < 24) {
            g_tile_ca(sm, (t + 1) & 1, Asrc, W, E_, tid, (t + 1) * 32);
            CP_COMMIT();
            CP_WAIT1();
        } else {
            CP_WAIT0();
        }
        __syncthreads();
        g_compute(sm, t & 1, wm, wn, lane, acc);
        __syncthreads();
    }

    const int w0 = 2 * (lane & 3);
    const int p0 = perm8(w0);
    const int p1 = perm8(w0 + 1);

    if (m < 2) {
        float* out = m == 0 ? q : k;
        #pragma unroll
        for (int mt = 0; mt < 2; ++mt) {
            #pragma unroll
            for (int rr = 0; rr < 2; ++rr) {
                int row = row0 + wm * 32 + mt * 16 + (lane >> 2) + rr * 8;
                int b_  = row / S_, s = row % S_;
                float* orow = out + ((size_t)(b_ * H_ + h) * S_ + s) * E_;
                #pragma unroll
                for (int nt = 0; nt < 4; ++nt) {
                    int eg = wn * 32 + nt * 8;
                    orow[eg + p0] = __uint_as_float(tf32cvt(acc[mt][nt][rr * 2    ] + bias[h * E_ + eg + w0]));
                    orow[eg + p1] = __uint_as_float(tf32cvt(acc[mt][nt][rr * 2 + 1] + bias[h * E_ + eg + w0 + 1]));
                }
            }
        }
    } else {
        #pragma unroll
        for (int mt = 0; mt < 2; ++mt) {
            #pragma unroll
            for (int rr = 0; rr < 2; ++rr) {
                int row = row0 + wm * 32 + mt * 16 + (lane >> 2) + rr * 8;
                int b_  = row / S_, s = row % S_;
                int spos = (s & ~7) + perm8(s & 7);
                #pragma unroll
                for (int nt = 0; nt < 4; ++nt) {
                    int e0 = wn * 32 + nt * 8 + w0;
                    vt[((size_t)(b_ * H_ + h) * E_ + e0    ) * S_ + spos] =
                        __uint_as_float(tf32cvt(acc[mt][nt][rr * 2    ] + bias[h * E_ + e0]));
                    vt[((size_t)(b_ * H_ + h) * E_ + e0 + 1) * S_ + spos] =
                        __uint_as_float(tf32cvt(acc[mt][nt][rr * 2 + 1] + bias[h * E_ + e0 + 1]));
                }
            }
        }
    }
}

// Output projection: grid (64, 12), unchanged.
__global__ void __launch_bounds__(256, 4) out_proj(
    const float* __restrict__ bO, float* __restrict__ out)
{
    extern __shared__ unsigned sm[];
    const int row0 = blockIdx.x * 128;
    const int n0   = blockIdx.y * 64;
    const int tid  = threadIdx.x;
    const int lane = tid & 31;
    const int wid  = tid >> 5;
    const int wm   = wid >> 1, wn = wid & 1;

    const float* Asrc = g_z + (size_t)row0 * D_;
    const float* Bsrc = g_wor + n0;

    float acc[2][4][4] = {};

    g_tile_ca(sm, 0, Asrc, Bsrc, D_, tid, 0);
    CP_COMMIT();
    for (int t = 0; t < 24; ++t) {
        if (t + 1 < 24) {
            g_tile_ca(sm, (t + 1) & 1, Asrc, Bsrc, D_, tid, (t + 1) * 32);
            CP_COMMIT();
            CP_WAIT1();
        } else {
            CP_WAIT0();
        }
        __syncthreads();
        g_compute(sm, t & 1, wm, wn, lane, acc);
        __syncthreads();
    }

    #pragma unroll
    for (int mt = 0; mt < 2; ++mt) {
        #pragma unroll
        for (int rr = 0; rr < 2; ++rr) {
            int row = row0 + wm * 32 + mt * 16 + (lane >> 2) + rr * 8;
            #pragma unroll
            for (int nt = 0; nt < 4; ++nt) {
                int d = n0 + wn * 32 + nt * 8 + 2 * (lane & 3);
                out[(size_t)row * D_ + d    ] = acc[mt][nt][rr * 2    ] + bO[d];
                out[(size_t)row * D_ + d + 1] = acc[mt][nt][rr * 2 + 1] + bO[d + 1];
            }
        }
    }
}

// ---------------------------------------------------------------------------
// Flash attention, fully pipelined:
//   - K/V double-buffered in smem (stride 72, conflict-free LDS.64)
//   - Q fragments in registers (one-time LDG.64s from interleaved g_q)
//   - P kept in registers; C-frag -> A-frag via quad shfl transpose
//   - one __syncthreads per jt; loads for jt+1 overlap compute of jt
//   - LPT: longest CTAs (high qt) launch first
// Smem: K0,K1,V0,V1 = 4 * 64*72 words = 73728 B -> 3 CTAs/SM.
// ---------------------------------------------------------------------------
#define ST_W   72
#define ST_U2  36
#define TILE_W (64 * ST_W)
#define AT_SMEM (4 * TILE_W * 4)

__global__ void __launch_bounds__(128, 3) attn_kernel()
{
    extern __shared__ unsigned sm_u[];

    const int qt  = (S_ / 64 - 1) - blockIdx.x;   // LPT: long CTAs first
    const int h   = blockIdx.y;
    const int b   = blockIdx.z;
    const int tid = threadIdx.x;
    const int lane = tid & 31;
    const int w    = tid >> 5;
    const int lc   = lane & 3;

    const size_t bh  = ((size_t)(b * H_ + h)) * S_ * E_;   // q/k base
    const size_t bhv = ((size_t)(b * H_ + h)) * E_ * S_;   // vt base

    // ---- issue jt=0 K/V loads
    {
        unsigned* K0 = sm_u;
        unsigned* V0 = sm_u + 2 * TILE_W;
        #pragma unroll
        for (int i = 0; i < 8; ++i) {
            int idx = tid + i * 128;
            int r = idx >> 4, c4 = (idx & 15) * 4;
            cp16(smem_u32(&K0[r * ST_W + c4]), &g_k[bh + (size_t)r * E_ + c4]);
            cp16(smem_u32(&V0[r * ST_W + c4]), &g_vt[bhv + (size_t)r * S_ + c4]);
        }
        CP_COMMIT();
    }

    // ---- Q fragments -> registers (interleaved gmem: frag pair is one LDG.64)
    const int ar = w * 16 + (lane >> 2);
    uint2 qa[8], qb[8];
    {
        const uint2* q0 = reinterpret_cast<const uint2*>(&g_q[bh + (size_t)(qt * 64 + ar) * E_]);
        const uint2* q1 = reinterpret_cast<const uint2*>(&g_q[bh + (size_t)(qt * 64 + ar + 8) * E_]);
        #pragma unroll
        for (int kt = 0; kt < 8; ++kt) {
            qa[kt] = q0[kt * 4 + lc];
            qb[kt] = q1[kt * 4 + lc];
        }
    }

    float o[8][4] = {};
    float m_[2] = { -1e30f, -1e30f };
    float l_[2] = { 0.f, 0.f };
    const float scale = 0.125f;

    const int w0   = 2 * lc;
    const int srcA = (lane & 28) | (lc >> 1);
    const int srcB = srcA + 2;
    const bool odd = lc & 1;

    for (int jt = 0; jt <= qt; ++jt) {
        const int buf = jt & 1;
        CP_WAIT0();
        __syncthreads();   // jt data visible to all; prev buffer free for reuse

        if (jt < qt) {     // issue jt+1 into the other buffer (overlaps compute)
            unsigned* Kn = sm_u + (buf ^ 1) * TILE_W;
            unsigned* Vn = sm_u + 2 * TILE_W + (buf ^ 1) * TILE_W;
            #pragma unroll
            for (int i = 0; i < 8; ++i) {
                int idx = tid + i * 128;
                int r = idx >> 4, c4 = (idx & 15) * 4;
                cp16(smem_u32(&Kn[r * ST_W + c4]),
                     &g_k[bh + (size_t)((jt + 1) * 64 + r) * E_ + c4]);
                cp16(smem_u32(&Vn[r * ST_W + c4]),
                     &g_vt[bhv + (size_t)r * S_ + (jt + 1) * 64 + c4]);
            }
            CP_COMMIT();
        }

        const uint2* K2 = reinterpret_cast<const uint2*>(sm_u + buf * TILE_W);
        const uint2* V2 = reinterpret_cast<const uint2*>(sm_u + 2 * TILE_W + buf * TILE_W);

        // ---- S = Q K^T  (Q regs, K LDS.64)
        float s[8][4] = {};
        #pragma unroll
        for (int kk = 0; kk < 8; ++kk) {
            #pragma unroll
            for (int nt = 0; nt < 8; ++nt) {
                uint2 bk = K2[(nt * 8 + (lane >> 2)) * ST_U2 + kk * 4 + lc];
                mma8(s[nt], qa[kk].x, qb[kk].x, qa[kk].y, qb[kk].y, bk.x, bk.y);
            }
        }

        // ---- scale + causal mask + online softmax
        const int qrow0 = qt * 64 + w * 16 + (lane >> 2);
        float mnew0 = m_[0], mnew1 = m_[1];
        #pragma unroll
        for (int nt = 0; nt < 8; ++nt) {
            int col = jt * 64 + nt * 8 + w0;
            float v0 = s[nt][0] * scale;
            float v1 = s[nt][1] * scale;
            float v2 = s[nt][2] * scale;
            float v3 = s[nt][3] * scale;
            if (jt == qt) {
                if (col     > qrow0)     v0 = -1e30f;
                if (col + 1 > qrow0)     v1 = -1e30f;
                if (col     > qrow0 + 8) v2 = -1e30f;
                if (col + 1 > qrow0 + 8) v3 = -1e30f;
            }
            s[nt][0] = v0; s[nt][1] = v1; s[nt][2] = v2; s[nt][3] = v3;
            mnew0 = fmaxf(mnew0, fmaxf(v0, v1));
            mnew1 = fmaxf(mnew1, fmaxf(v2, v3));
        }
        mnew0 = fmaxf(mnew0, __shfl_xor_sync(0xffffffffu, mnew0, 1));
        mnew0 = fmaxf(mnew0, __shfl_xor_sync(0xffffffffu, mnew0, 2));
        mnew1 = fmaxf(mnew1, __shfl_xor_sync(0xffffffffu, mnew1, 1));
        mnew1 = fmaxf(mnew1, __shfl_xor_sync(0xffffffffu, mnew1, 2));

        float f0 = __expf(m_[0] - mnew0);
        float f1 = __expf(m_[1] - mnew1);
        float sum0 = 0.f, sum1 = 0.f;
        #pragma unroll
        for (int nt = 0; nt < 8; ++nt) {
            s[nt][0] = __expf(s[nt][0] - mnew0);
            s[nt][1] = __expf(s[nt][1] - mnew0);
            s[nt][2] = __expf(s[nt][2] - mnew1);
            s[nt][3] = __expf(s[nt][3] - mnew1);
            sum0 += s[nt][0] + s[nt][1];
            sum1 += s[nt][2] + s[nt][3];
        }
        sum0 += __shfl_xor_sync(0xffffffffu, sum0, 1);
        sum0 += __shfl_xor_sync(0xffffffffu, sum0, 2);
        sum1 += __shfl_xor_sync(0xffffffffu, sum1, 1);
        sum1 += __shfl_xor_sync(0xffffffffu, sum1, 2);
        l_[0] = l_[0] * f0 + sum0;
        l_[1] = l_[1] * f1 + sum1;
        m_[0] = mnew0;
        m_[1] = mnew1;

        #pragma unroll
        for (int nt = 0; nt < 8; ++nt) {
            o[nt][0] *= f0; o[nt][1] *= f0;
            o[nt][2] *= f1; o[nt][3] *= f1;
        }

        // ---- O += P @ V.  P C-frag -> A-frag via quad shfl transpose:
        //   target lane q needs P[r0][kt*8+q] etc.; source lane (q>>1)/(q>>1)+2
        //   holds it as element (q&1) of its (c0,c1)/(c2,c3) pairs.
        #pragma unroll
        for (int kt = 0; kt < 8; ++kt) {
            float t0 = __shfl_sync(0xffffffffu, s[kt][0], srcA);
            float t1 = __shfl_sync(0xffffffffu, s[kt][1], srcA);
            float t2 = __shfl_sync(0xffffffffu, s[kt][2], srcA);
            float t3 = __shfl_sync(0xffffffffu, s[kt][3], srcA);
            float u0 = __shfl_sync(0xffffffffu, s[kt][0], srcB);
            float u1 = __shfl_sync(0xffffffffu, s[kt][1], srcB);
            float u2 = __shfl_sync(0xffffffffu, s[kt][2], srcB);
            float u3 = __shfl_sync(0xffffffffu, s[kt][3], srcB);
            unsigned A0 = tf32cvt(odd ? t1 : t0);   // P[r0   ][kt*8+q]
            unsigned A1 = tf32cvt(odd ? t3 : t2);   // P[r0+8 ][kt*8+q]
            unsigned A2 = tf32cvt(odd ? u1 : u0);   // P[r0   ][kt*8+q+4]
            unsigned A3 = tf32cvt(odd ? u3 : u2);   // P[r0+8 ][kt*8+q+4]
            #pragma unroll
            for (int nt = 0; nt < 8; ++nt) {
                uint2 bv = V2[(nt * 8 + (lane >> 2)) * ST_U2 + kt * 4 + lc];
                mma8(o[nt], A0, A1, A2, A3, bv.x, bv.y);
            }
        }
        // no end-of-loop barrier: next iteration's top syncthreads covers reuse
    }

    // ---- normalize + write z (tf32-rounded; out_proj consumes raw)
    float inv0 = 1.0f / l_[0];
    float inv1 = 1.0f / l_[1];
    int qr = qt * 64 + w * 16 + (lane >> 2);
    #pragma unroll
    for (int nt = 0; nt < 8; ++nt) {
        int e = nt * 8 + w0;
        size_t base0 = (size_t)(b * S_ + qr) * D_ + h * E_ + e;
        size_t base1 = (size_t)(b * S_ + qr + 8) * D_ + h * E_ + e;
        g_z[base0    ] = __uint_as_float(tf32cvt(o[nt][0] * inv0));
        g_z[base0 + 1] = __uint_as_float(tf32cvt(o[nt][1] * inv0));
        g_z[base1    ] = __uint_as_float(tf32cvt(o[nt][2] * inv1));
        g_z[base1 + 1] = __uint_as_float(tf32cvt(o[nt][3] * inv1));
    }
}

// ---------------------------------------------------------------------------
extern "C" void kernel_launch(void* const* d_in, const int* in_sizes, int n_in,
                              void* d_out, int out_size)
{
    const float* x  = (const float*)d_in[0];
    const float* WQ = (const float*)d_in[1];
    const float* WK = (const float*)d_in[2];
    const float* WV = (const float*)d_in[3];
    const float* WO = (const float*)d_in[4];
    const float* bQ = (const float*)d_in[5];
    const float* bK = (const float*)d_in[6];
    const float* bV = (const float*)d_in[7];
    const float* bO = (const float*)d_in[8];
    float* out = (float*)d_out;

    float *q, *k, *vt, *xt, *wqr, *wkr, *wvr, *wor;
    cudaGetSymbolAddress((void**)&q,   g_q);
    cudaGetSymbolAddress((void**)&k,   g_k);
    cudaGetSymbolAddress((void**)&vt,  g_vt);
    cudaGetSymbolAddress((void**)&xt,  g_xt);
    cudaGetSymbolAddress((void**)&wqr, g_wqr);
    cudaGetSymbolAddress((void**)&wkr, g_wkr);
    cudaGetSymbolAddress((void**)&wvr, g_wvr);
    cudaGetSymbolAddress((void**)&wor, g_wor);

    // Pre-round everything to tf32
    const int n4x = BS_ * D_ / 4;
    const int n4w = H_ * D_ * E_ / 4;
    const int n4o = D_ * D_ / 4;
    round_tf32<<<(n4x + 255) / 256, 256>>>(x,  xt,  n4x);
    round_tf32<<<(n4w + 255) / 256, 256>>>(WQ, wqr, n4w);
    round_tf32<<<(n4w + 255) / 256, 256>>>(WK, wkr, n4w);
    round_tf32<<<(n4w + 255) / 256, 256>>>(WV, wvr, n4w);
    round_tf32<<<(n4o + 255) / 256, 256>>>(WO, wor, n4o);

    // QKV projections (cp.async double-buffered)
    cudaFuncSetAttribute(qkv_gemm, cudaFuncAttributeMaxDynamicSharedMemorySize, G_SMEM_B);
    qkv_gemm<<<dim3(BS_ / 128, H_, 3), 256, G_SMEM_B>>>(bQ, bK, bV, q, k, vt);

    // Flash attention (pipelined K/V, register P, LPT)
    cudaFuncSetAttribute(attn_kernel, cudaFuncAttributeMaxDynamicSharedMemorySize, AT_SMEM);
    attn_kernel<<<dim3(S_ / 64, H_, B_), 128, AT_SMEM>>>();

    // Output projection (cp.async double-buffered)
    cudaFuncSetAttribute(out_proj, cudaFuncAttributeMaxDynamicSharedMemorySize, G_SMEM_B);
    out_proj<<<dim3(BS_ / 128, D_ / 64), 256, G_SMEM_B>>>(bO, out);
}

// round 17
// speedup vs baseline: 1.4620x; 1.4620x over previous
#include <cuda_runtime.h>
#include <cstdint>
#include <math.h>

#define B_  4
#define S_  2048
#define D_  768
#define H_  12
#define E_  64
#define BS_ (B_ * S_)   // 8192

// Scratch (static device globals: allocation-free per harness rules)
__device__ float g_q[(size_t)B_ * H_ * S_ * E_];   // [bh][s][e-interleaved]
__device__ float g_k[(size_t)B_ * H_ * S_ * E_];   // [bh][s][e-interleaved]
__device__ float g_vt[(size_t)B_ * H_ * E_ * S_];  // [bh][e][s-interleaved]
__device__ float g_z[(size_t)BS_ * D_];
__device__ float g_xt [(size_t)BS_ * D_];          // x, tf32-rounded
__device__ float g_wqr[(size_t)H_ * D_ * E_];      // W_Q, tf32-rounded
__device__ float g_wkr[(size_t)H_ * D_ * E_];
__device__ float g_wvr[(size_t)H_ * D_ * E_];
__device__ float g_wor[(size_t)D_ * D_];           // W_O, tf32-rounded

// ---------------------------------------------------------------------------
__device__ __forceinline__ unsigned tf32cvt(float f) {
    unsigned u;
    asm("cvt.rna.tf32.f32 %0, %1;" : "=r"(u) : "f"(f));
    return u;
}

__device__ __forceinline__ void mma8(float c[4],
                                     unsigned a0, unsigned a1, unsigned a2, unsigned a3,
                                     unsigned b0, unsigned b1) {
    asm volatile(
        "mma.sync.aligned.m16n8k8.row.col.f32.tf32.tf32.f32 "
        "{%0,%1,%2,%3}, {%4,%5,%6,%7}, {%8,%9}, {%0,%1,%2,%3};\n"
        : "+f"(c[0]), "+f"(c[1]), "+f"(c[2]), "+f"(c[3])
        : "r"(a0), "r"(a1), "r"(a2), "r"(a3), "r"(b0), "r"(b1));
}

__device__ __forceinline__ uint32_t smem_u32(const void* p) {
    uint32_t a;
    asm("{ .reg .u64 t; cvta.to.shared.u64 t, %1; cvt.u32.u64 %0, t; }" : "=r"(a) : "l"(p));
    return a;
}

__device__ __forceinline__ void cp16(uint32_t dst, const void* src) {
    asm volatile("cp.async.cg.shared.global [%0], [%1], 16;" :: "r"(dst), "l"(src));
}
#define CP_COMMIT() asm volatile("cp.async.commit_group;" ::: "memory")
#define CP_WAIT0()  asm volatile("cp.async.wait_group 0;" ::: "memory")
#define CP_WAIT1()  asm volatile("cp.async.wait_group 1;" ::: "memory")

// pair-interleave within 8-groups: w -> (w<4 ? 2w : 2w-7)
__device__ __forceinline__ int perm8(int w) { return (w < 4) ? 2 * w : 2 * w - 7; }

// ---------------------------------------------------------------------------
__global__ void __launch_bounds__(256) round_tf32(
    const float* __restrict__ s, float* __restrict__ d, int n4)
{
    int i = blockIdx.x * 256 + threadIdx.x;
    if (i < n4) {
        float4 f = reinterpret_cast<const float4*>(s)[i];
        uint4 u = { tf32cvt(f.x), tf32cvt(f.y), tf32cvt(f.z), tf32cvt(f.w) };
        reinterpret_cast<uint4*>(d)[i] = u;
    }
}

// ---------------------------------------------------------------------------
// cp.async double-buffered GEMM core (unchanged from round 15).
// ---------------------------------------------------------------------------
#define A_W(b)   ((b) * 4608)
#define B_W(b)   (9216 + (b) * 2304)
#define G_SMEM_B 55296

__device__ __forceinline__ void g_tile_ca(
    unsigned* sm, int buf, const float* __restrict__ Asrc,
    const float* __restrict__ Bsrc, int bstride, int tid, int k0)
{
    #pragma unroll
    for (int i = 0; i < 4; ++i) {
        int idx = tid + i * 256;
        int r = idx >> 3, c4 = (idx & 7) * 4;
        cp16(smem_u32(&sm[A_W(buf) + r * 36 + c4]),
             Asrc + (size_t)r * D_ + k0 + c4);
    }
    #pragma unroll
    for (int i = 0; i < 2; ++i) {
        int idx = tid + i * 256;
        int r = idx >> 4, c4 = (idx & 15) * 4;
        cp16(smem_u32(&sm[B_W(buf) + r * 72 + c4]),
             Bsrc + (size_t)(k0 + r) * bstride + c4);
    }
}

__device__ __forceinline__ void g_compute(
    const unsigned* sm, int buf, int wm, int wn, int lane, float acc[2][4][4])
{
    const unsigned* As = sm + A_W(buf);
    const unsigned* Bs = sm + B_W(buf);
    #pragma unroll
    for (int kk = 0; kk < 4; ++kk) {
        const int ac = kk * 8 + (lane & 3);
        const int ar = wm * 32 + (lane >> 2);
        unsigned a[2][4];
        #pragma unroll
        for (int mt = 0; mt < 2; ++mt) {
            a[mt][0] = As[(ar + mt * 16    ) * 36 + ac];
            a[mt][1] = As[(ar + mt * 16 + 8) * 36 + ac];
            a[mt][2] = As[(ar + mt * 16    ) * 36 + ac + 4];
            a[mt][3] = As[(ar + mt * 16 + 8) * 36 + ac + 4];
        }
        const int bk = kk * 8 + (lane & 3);
        const int bn = wn * 32 + (lane >> 2);
        unsigned b[4][2];
        #pragma unroll
        for (int nt = 0; nt < 4; ++nt) {
            b[nt][0] = Bs[bk * 72 + bn + nt * 8];
            b[nt][1] = Bs[(bk + 4) * 72 + bn + nt * 8];
        }
        #pragma unroll
        for (int mt = 0; mt < 2; ++mt)
            #pragma unroll
            for (int nt = 0; nt < 4; ++nt)
                mma8(acc[mt][nt], a[mt][0], a[mt][1], a[mt][2], a[mt][3],
                     b[nt][0], b[nt][1]);
    }
}

// QKV projection: grid (64, H, 3). Q/K stored e-interleaved; V transposed,
// s-interleaved. All values tf32-rounded (consumed raw by attn).
__global__ void __launch_bounds__(256, 4) qkv_gemm(
    const float* __restrict__ bQ, const float* __restrict__ bK, const float* __restrict__ bV,
    float* __restrict__ q, float* __restrict__ k, float* __restrict__ vt)
{
    extern __shared__ unsigned sm[];
    const int row0 = blockIdx.x * 128;
    const int h    = blockIdx.y;
    const int m    = blockIdx.z;
    const int tid  = threadIdx.x;
    const int lane = tid & 31;
    const int wid  = tid >> 5;
    const int wm   = wid >> 1, wn = wid & 1;

    const float* Asrc = g_xt + (size_t)row0 * D_;
    const float* W    = (m == 0 ? g_wqr : m == 1 ? g_wkr : g_wvr) + (size_t)h * D_ * E_;
    const float* bias = m == 0 ? bQ : m == 1 ? bK : bV;

    float acc[2][4][4] = {};

    g_tile_ca(sm, 0, Asrc, W, E_, tid, 0);
    CP_COMMIT();
    for (int t = 0; t < 24; ++t) {
        if (t + 1 < 24) {
            g_tile_ca(sm, (t + 1) & 1, Asrc, W, E_, tid, (t + 1) * 32);
            CP_COMMIT();
            CP_WAIT1();
        } else {
            CP_WAIT0();
        }
        __syncthreads();
        g_compute(sm, t & 1, wm, wn, lane, acc);
        __syncthreads();
    }

    const int w0 = 2 * (lane & 3);
    const int p0 = perm8(w0);
    const int p1 = perm8(w0 + 1);

    if (m < 2) {
        float* out = m == 0 ? q : k;
        #pragma unroll
        for (int mt = 0; mt < 2; ++mt) {
            #pragma unroll
            for (int rr = 0; rr < 2; ++rr) {
                int row = row0 + wm * 32 + mt * 16 + (lane >> 2) + rr * 8;
                int b_  = row / S_, s = row % S_;
                float* orow = out + ((size_t)(b_ * H_ + h) * S_ + s) * E_;
                #pragma unroll
                for (int nt = 0; nt < 4; ++nt) {
                    int eg = wn * 32 + nt * 8;
                    orow[eg + p0] = __uint_as_float(tf32cvt(acc[mt][nt][rr * 2    ] + bias[h * E_ + eg + w0]));
                    orow[eg + p1] = __uint_as_float(tf32cvt(acc[mt][nt][rr * 2 + 1] + bias[h * E_ + eg + w0 + 1]));
                }
            }
        }
    } else {
        #pragma unroll
        for (int mt = 0; mt < 2; ++mt) {
            #pragma unroll
            for (int rr = 0; rr < 2; ++rr) {
                int row = row0 + wm * 32 + mt * 16 + (lane >> 2) + rr * 8;
                int b_  = row / S_, s = row % S_;
                int spos = (s & ~7) + perm8(s & 7);
                #pragma unroll
                for (int nt = 0; nt < 4; ++nt) {
                    int e0 = wn * 32 + nt * 8 + w0;
                    vt[((size_t)(b_ * H_ + h) * E_ + e0    ) * S_ + spos] =
                        __uint_as_float(tf32cvt(acc[mt][nt][rr * 2    ] + bias[h * E_ + e0]));
                    vt[((size_t)(b_ * H_ + h) * E_ + e0 + 1) * S_ + spos] =
                        __uint_as_float(tf32cvt(acc[mt][nt][rr * 2 + 1] + bias[h * E_ + e0 + 1]));
                }
            }
        }
    }
}

// Output projection: grid (64, 12), unchanged.
__global__ void __launch_bounds__(256, 4) out_proj(
    const float* __restrict__ bO, float* __restrict__ out)
{
    extern __shared__ unsigned sm[];
    const int row0 = blockIdx.x * 128;
    const int n0   = blockIdx.y * 64;
    const int tid  = threadIdx.x;
    const int lane = tid & 31;
    const int wid  = tid >> 5;
    const int wm   = wid >> 1, wn = wid & 1;

    const float* Asrc = g_z + (size_t)row0 * D_;
    const float* Bsrc = g_wor + n0;

    float acc[2][4][4] = {};

    g_tile_ca(sm, 0, Asrc, Bsrc, D_, tid, 0);
    CP_COMMIT();
    for (int t = 0; t < 24; ++t) {
        if (t + 1 < 24) {
            g_tile_ca(sm, (t + 1) & 1, Asrc, Bsrc, D_, tid, (t + 1) * 32);
            CP_COMMIT();
            CP_WAIT1();
        } else {
            CP_WAIT0();
        }
        __syncthreads();
        g_compute(sm, t & 1, wm, wn, lane, acc);
        __syncthreads();
    }

    #pragma unroll
    for (int mt = 0; mt < 2; ++mt) {
        #pragma unroll
        for (int rr = 0; rr < 2; ++rr) {
            int row = row0 + wm * 32 + mt * 16 + (lane >> 2) + rr * 8;
            #pragma unroll
            for (int nt = 0; nt < 4; ++nt) {
                int d = n0 + wn * 32 + nt * 8 + 2 * (lane & 3);
                out[(size_t)row * D_ + d    ] = acc[mt][nt][rr * 2    ] + bO[d];
                out[(size_t)row * D_ + d + 1] = acc[mt][nt][rr * 2 + 1] + bO[d + 1];
            }
        }
    }
}

// ---------------------------------------------------------------------------
// Flash attention (round-15 base + register Q + dedicated P buffer + LPT):
//   Smem: Ks[64][72] | Vs[64][72] | Ps[64][72]  (54 KB -> 4 CTAs)
//   Q fragments live in registers (one-time LDG.64s from interleaved g_q).
//   P is warp-private (each warp stores/reads only its own 16 rows of Ps)
//   -> no barrier between QK^T and the P store; 2 syncthreads per jt.
// ---------------------------------------------------------------------------
#define ST_W   72
#define ST_U2  36
#define TILE_W (64 * ST_W)
#define AT_SMEM (3 * TILE_W * 4)

__global__ void __launch_bounds__(128, 4) attn_kernel()
{
    extern __shared__ unsigned sm_u[];
    unsigned* Ks = sm_u;
    unsigned* Vs = sm_u + TILE_W;
    unsigned* Ps = sm_u + 2 * TILE_W;
    const uint2* K2 = reinterpret_cast<const uint2*>(Ks);
    const uint2* V2 = reinterpret_cast<const uint2*>(Vs);
    const uint2* P2 = reinterpret_cast<const uint2*>(Ps);

    const int qt  = (S_ / 64 - 1) - blockIdx.x;   // LPT: long CTAs first
    const int h   = blockIdx.y;
    const int b   = blockIdx.z;
    const int tid = threadIdx.x;
    const int lane = tid & 31;
    const int w    = tid >> 5;
    const int lc   = lane & 3;

    const size_t bh  = ((size_t)(b * H_ + h)) * S_ * E_;   // q/k base
    const size_t bhv = ((size_t)(b * H_ + h)) * E_ * S_;   // vt base

    // ---- Q fragments -> registers (interleaved gmem: frag pair is one LDG.64)
    const int ar = w * 16 + (lane >> 2);
    uint2 qa[8], qb[8];
    {
        const uint2* q0 = reinterpret_cast<const uint2*>(&g_q[bh + (size_t)(qt * 64 + ar) * E_]);
        const uint2* q1 = reinterpret_cast<const uint2*>(&g_q[bh + (size_t)(qt * 64 + ar + 8) * E_]);
        #pragma unroll
        for (int kt = 0; kt < 8; ++kt) {
            qa[kt] = q0[kt * 4 + lc];
            qb[kt] = q1[kt * 4 + lc];
        }
    }

    float o[8][4] = {};
    float m_[2] = { -1e30f, -1e30f };
    float l_[2] = { 0.f, 0.f };
    const float scale = 0.125f;

    const int w0  = 2 * lc;
    const int pp0 = perm8(w0);
    const int pp1 = perm8(w0 + 1);

    for (int jt = 0; jt <= qt; ++jt) {
        // ---- K tile [key][e-int], V tile [e][key-int] via cp.async
        #pragma unroll
        for (int i = 0; i < 8; ++i) {
            int idx = tid + i * 128;
            int r = idx >> 4, c4 = (idx & 15) * 4;
            cp16(smem_u32(&Ks[r * ST_W + c4]),
                 &g_k[bh + (size_t)(jt * 64 + r) * E_ + c4]);
            cp16(smem_u32(&Vs[r * ST_W + c4]),
                 &g_vt[bhv + (size_t)r * S_ + jt * 64 + c4]);
        }
        CP_COMMIT(); CP_WAIT0();
        __syncthreads();

        // ---- S = Q K^T  (Q regs, K LDS.64)
        float s[8][4] = {};
        #pragma unroll
        for (int kk = 0; kk < 8; ++kk) {
            #pragma unroll
            for (int nt = 0; nt < 8; ++nt) {
                uint2 bk = K2[(nt * 8 + (lane >> 2)) * ST_U2 + kk * 4 + lc];
                mma8(s[nt], qa[kk].x, qb[kk].x, qa[kk].y, qb[kk].y, bk.x, bk.y);
            }
        }

        // ---- scale + causal mask + online softmax
        const int qrow0 = qt * 64 + w * 16 + (lane >> 2);
        float mnew0 = m_[0], mnew1 = m_[1];
        #pragma unroll
        for (int nt = 0; nt < 8; ++nt) {
            int col = jt * 64 + nt * 8 + w0;
            float v0 = s[nt][0] * scale;
            float v1 = s[nt][1] * scale;
            float v2 = s[nt][2] * scale;
            float v3 = s[nt][3] * scale;
            if (jt == qt) {
                if (col     > qrow0)     v0 = -1e30f;
                if (col + 1 > qrow0)     v1 = -1e30f;
                if (col     > qrow0 + 8) v2 = -1e30f;
                if (col + 1 > qrow0 + 8) v3 = -1e30f;
            }
            s[nt][0] = v0; s[nt][1] = v1; s[nt][2] = v2; s[nt][3] = v3;
            mnew0 = fmaxf(mnew0, fmaxf(v0, v1));
            mnew1 = fmaxf(mnew1, fmaxf(v2, v3));
        }
        mnew0 = fmaxf(mnew0, __shfl_xor_sync(0xffffffffu, mnew0, 1));
        mnew0 = fmaxf(mnew0, __shfl_xor_sync(0xffffffffu, mnew0, 2));
        mnew1 = fmaxf(mnew1, __shfl_xor_sync(0xffffffffu, mnew1, 1));
        mnew1 = fmaxf(mnew1, __shfl_xor_sync(0xffffffffu, mnew1, 2));

        float f0 = __expf(m_[0] - mnew0);
        float f1 = __expf(m_[1] - mnew1);
        float sum0 = 0.f, sum1 = 0.f;
        #pragma unroll
        for (int nt = 0; nt < 8; ++nt) {
            s[nt][0] = __expf(s[nt][0] - mnew0);
            s[nt][1] = __expf(s[nt][1] - mnew0);
            s[nt][2] = __expf(s[nt][2] - mnew1);
            s[nt][3] = __expf(s[nt][3] - mnew1);
            sum0 += s[nt][0] + s[nt][1];
            sum1 += s[nt][2] + s[nt][3];
        }
        sum0 += __shfl_xor_sync(0xffffffffu, sum0, 1);
        sum0 += __shfl_xor_sync(0xffffffffu, sum0, 2);
        sum1 += __shfl_xor_sync(0xffffffffu, sum1, 1);
        sum1 += __shfl_xor_sync(0xffffffffu, sum1, 2);
        l_[0] = l_[0] * f0 + sum0;
        l_[1] = l_[1] * f1 + sum1;
        m_[0] = mnew0;
        m_[1] = mnew1;

        #pragma unroll
        for (int nt = 0; nt < 8; ++nt) {
            o[nt][0] *= f0; o[nt][1] *= f0;
            o[nt][2] *= f1; o[nt][3] *= f1;
        }

        // ---- store P interleaved into warp-private rows of Ps (no CTA barrier)
        {
            int pr = w * 16 + (lane >> 2);
            #pragma unroll
            for (int nt = 0; nt < 8; ++nt) {
                int base = nt * 8;
                Ps[(pr    ) * ST_W + base + pp0] = tf32cvt(s[nt][0]);
                Ps[(pr    ) * ST_W + base + pp1] = tf32cvt(s[nt][1]);
                Ps[(pr + 8) * ST_W + base + pp0] = tf32cvt(s[nt][2]);
                Ps[(pr + 8) * ST_W + base + pp1] = tf32cvt(s[nt][3]);
            }
        }
        __syncwarp();   // P@V reads only this warp's rows of Ps

        // ---- O += P @ V  (LDS.64 fragments)
        #pragma unroll
        for (int kt = 0; kt < 8; ++kt) {
            int pi = ar * ST_U2 + kt * 4 + lc;
            uint2 pa = P2[pi];
            uint2 pb = P2[pi + 8 * ST_U2];
            #pragma unroll
            for (int nt = 0; nt < 8; ++nt) {
                uint2 bv = V2[(nt * 8 + (lane >> 2)) * ST_U2 + kt * 4 + lc];
                mma8(o[nt], pa.x, pb.x, pa.y, pb.y, bv.x, bv.y);
            }
        }
        __syncthreads();   // guard K/V reload next jt
    }

    // ---- normalize + write z (tf32-rounded; out_proj consumes raw)
    float inv0 = 1.0f / l_[0];
    float inv1 = 1.0f / l_[1];
    int qr = qt * 64 + w * 16 + (lane >> 2);
    #pragma unroll
    for (int nt = 0; nt < 8; ++nt) {
        int e = nt * 8 + w0;
        size_t base0 = (size_t)(b * S_ + qr) * D_ + h * E_ + e;
        size_t base1 = (size_t)(b * S_ + qr + 8) * D_ + h * E_ + e;
        g_z[base0    ] = __uint_as_float(tf32cvt(o[nt][0] * inv0));
        g_z[base0 + 1] = __uint_as_float(tf32cvt(o[nt][1] * inv0));
        g_z[base1    ] = __uint_as_float(tf32cvt(o[nt][2] * inv1));
        g_z[base1 + 1] = __uint_as_float(tf32cvt(o[nt][3] * inv1));
    }
}

// ---------------------------------------------------------------------------
extern "C" void kernel_launch(void* const* d_in, const int* in_sizes, int n_in,
                              void* d_out, int out_size)
{
    const float* x  = (const float*)d_in[0];
    const float* WQ = (const float*)d_in[1];
    const float* WK = (const float*)d_in[2];
    const float* WV = (const float*)d_in[3];
    const float* WO = (const float*)d_in[4];
    const float* bQ = (const float*)d_in[5];
    const float* bK = (const float*)d_in[6];
    const float* bV = (const float*)d_in[7];
    const float* bO = (const float*)d_in[8];
    float* out = (float*)d_out;

    float *q, *k, *vt, *xt, *wqr, *wkr, *wvr, *wor;
    cudaGetSymbolAddress((void**)&q,   g_q);
    cudaGetSymbolAddress((void**)&k,   g_k);
    cudaGetSymbolAddress((void**)&vt,  g_vt);
    cudaGetSymbolAddress((void**)&xt,  g_xt);
    cudaGetSymbolAddress((void**)&wqr, g_wqr);
    cudaGetSymbolAddress((void**)&wkr, g_wkr);
    cudaGetSymbolAddress((void**)&wvr, g_wvr);
    cudaGetSymbolAddress((void**)&wor, g_wor);

    // Pre-round everything to tf32
    const int n4x = BS_ * D_ / 4;
    const int n4w = H_ * D_ * E_ / 4;
    const int n4o = D_ * D_ / 4;
    round_tf32<<<(n4x + 255) / 256, 256>>>(x,  xt,  n4x);
    round_tf32<<<(n4w + 255) / 256, 256>>>(WQ, wqr, n4w);
    round_tf32<<<(n4w + 255) / 256, 256>>>(WK, wkr, n4w);
    round_tf32<<<(n4w + 255) / 256, 256>>>(WV, wvr, n4w);
    round_tf32<<<(n4o + 255) / 256, 256>>>(WO, wor, n4o);

    // QKV projections (cp.async double-buffered)
    cudaFuncSetAttribute(qkv_gemm, cudaFuncAttributeMaxDynamicSharedMemorySize, G_SMEM_B);
    qkv_gemm<<<dim3(BS_ / 128, H_, 3), 256, G_SMEM_B>>>(bQ, bK, bV, q, k, vt);

    // Flash attention (register Q, dedicated P buffer, LPT)
    cudaFuncSetAttribute(attn_kernel, cudaFuncAttributeMaxDynamicSharedMemorySize, AT_SMEM);
    attn_kernel<<<dim3(S_ / 64, H_, B_), 128, AT_SMEM>>>();

    // Output projection (cp.async double-buffered)
    cudaFuncSetAttribute(out_proj, cudaFuncAttributeMaxDynamicSharedMemorySize, G_SMEM_B);
    out_proj<<<dim3(BS_ / 128, D_ / 64), 256, G_SMEM_B>>>(bO, out);
}